// round 10
// baseline (speedup 1.0000x reference)
#include <cuda_runtime.h>
#include <cstdint>

// Problem constants
#define CB_K     512
#define CB_HALF  256
#define EMB_D    64
#define N_ROWS   65536
#define THREADS  256
#define ROWS_PER_CTA 512                 // 256 thr * 2 rows
#define N_CTA    (N_ROWS / ROWS_PER_CTA) // 128
#define Q_ELEMS  ((size_t)N_ROWS * EMB_D)

// smem: low-half codebook [256][64] + sc[512] + red[256]
#define SMEM_FLOATS (CB_HALF * EMB_D + CB_K + THREADS)
#define SMEM_BYTES  (SMEM_FLOATS * 4)

__device__  float g_partial[N_CTA];
__constant__ float c_ehi[CB_HALF * EMB_D];   // codes 256..511 (exactly 64 KB)

// ---- packed f32x2 helpers (force FFMA2 in SASS) ----
__device__ __forceinline__ unsigned long long fma2(unsigned long long a,
                                                   unsigned long long b,
                                                   unsigned long long c) {
    unsigned long long r;
    asm("fma.rn.f32x2 %0, %1, %2, %3;" : "=l"(r) : "l"(a), "l"(b), "l"(c));
    return r;
}
__device__ __forceinline__ unsigned long long add2(unsigned long long a,
                                                   unsigned long long b) {
    unsigned long long r;
    asm("add.rn.f32x2 %0, %1, %2;" : "=l"(r) : "l"(a), "l"(b));
    return r;
}
__device__ __forceinline__ unsigned long long pk2(float lo, float hi) {
    unsigned long long r;
    asm("mov.b64 %0, {%1, %2};" : "=l"(r) : "f"(lo), "f"(hi));
    return r;
}
__device__ __forceinline__ float lo2(unsigned long long v) {
    return __uint_as_float((unsigned)(v & 0xffffffffull));
}
__device__ __forceinline__ float hi2(unsigned long long v) {
    return __uint_as_float((unsigned)(v >> 32));
}

// R8 shape (256 thr, 2 rows/thread, 1 CTA/SM) but per iteration handles code k
// from SMEM and code k+256 from CONSTANT memory -> e-load traffic split across
// two independent ports. Numerics of every d_k bit-identical to R8.
__global__ void __launch_bounds__(THREADS, 1)
vq_main_kernel(const float* __restrict__ x_g,
               const float* __restrict__ e_g,
               float* __restrict__ out) {
    extern __shared__ float smem[];
    float* se   = smem;                    // [256][64] low half
    float* sc   = smem + CB_HALF * EMB_D;  // [512] |e_k|^2 (both halves)
    float* sred = sc + CB_K;               // [256] loss partials

    const int tid = threadIdx.x;

    // --- stage LOW half of codebook into smem (coalesced float4) ---
    {
        float4* se4 = reinterpret_cast<float4*>(se);
        const float4* eg4 = reinterpret_cast<const float4*>(e_g);
        #pragma unroll
        for (int i = 0; i < (CB_HALF * EMB_D / 4) / THREADS; i++)
            se4[tid + i * THREADS] = eg4[tid + i * THREADS];
    }
    __syncthreads();

    // --- |e_k|^2 : low half from smem, high half from const (same bits) ---
    {
        const float* er = se + tid * EMB_D;
        float s = 0.f;
        #pragma unroll 16
        for (int d = 0; d < EMB_D; d++) s = __fmaf_rn(er[d], er[d], s);
        sc[tid] = s;

        const float* eh = c_ehi + tid * EMB_D;
        float t = 0.f;
        #pragma unroll 16
        for (int d = 0; d < EMB_D; d++) t = __fmaf_rn(eh[d], eh[d], t);
        sc[CB_HALF + tid] = t;
    }
    __syncthreads();

    // --- load the two x rows into registers as f32x2 pairs ---
    const int row0 = blockIdx.x * ROWS_PER_CTA + tid;
    const int row1 = row0 + THREADS;
    unsigned long long xa[32], xb[32];
    {
        const float4* xr0 = reinterpret_cast<const float4*>(x_g + (size_t)row0 * EMB_D);
        const float4* xr1 = reinterpret_cast<const float4*>(x_g + (size_t)row1 * EMB_D);
        #pragma unroll
        for (int i = 0; i < 16; i++) {
            float4 f = xr0[i];
            xa[2 * i]     = pk2(f.x, f.y);
            xa[2 * i + 1] = pk2(f.z, f.w);
            float4 g = xr1[i];
            xb[2 * i]     = pk2(g.x, g.y);
            xb[2 * i + 1] = pk2(g.z, g.w);
        }
    }

    // --- A = |x|^2 per row (same summation tree as R8) ---
    float A0, A1;
    {
        unsigned long long a0 = 0, a1 = 0, a2 = 0, a3 = 0;
        unsigned long long b0 = 0, b1 = 0, b2 = 0, b3 = 0;
        #pragma unroll
        for (int i = 0; i < 32; i += 4) {
            a0 = fma2(xa[i],     xa[i],     a0);
            a1 = fma2(xa[i + 1], xa[i + 1], a1);
            a2 = fma2(xa[i + 2], xa[i + 2], a2);
            a3 = fma2(xa[i + 3], xa[i + 3], a3);
            b0 = fma2(xb[i],     xb[i],     b0);
            b1 = fma2(xb[i + 1], xb[i + 1], b1);
            b2 = fma2(xb[i + 2], xb[i + 2], b2);
            b3 = fma2(xb[i + 3], xb[i + 3], b3);
        }
        unsigned long long s0 = add2(add2(a0, a2), add2(a1, a3));
        unsigned long long s1 = add2(add2(b0, b2), add2(b1, b3));
        A0 = lo2(s0) + hi2(s0);
        A1 = lo2(s1) + hi2(s1);
    }

    // --- argmin: per iteration code k (P, smem) + code k+256 (Q, const).
    // d_k = fl(fl(A - 2*dot) + C): exact R8 association, bit-identical bits.
    float bestP0 = 3.4e38f, bestP1 = 3.4e38f, bestQ0 = 3.4e38f, bestQ1 = 3.4e38f;
    int   bkP0 = 0, bkP1 = 0, bkQ0 = 0, bkQ1 = 0;
    const ulonglong2* seu = reinterpret_cast<const ulonglong2*>(se);
    const ulonglong2* cqu = reinterpret_cast<const ulonglong2*>(c_ehi);
    for (int k = 0; k < CB_HALF; k++) {
        const ulonglong2* ep = seu + k * 16;
        const ulonglong2* eq = cqu + k * 16;
        unsigned long long pa0 = 0, pa1 = 0, pa2 = 0, pa3 = 0;
        unsigned long long pb0 = 0, pb1 = 0, pb2 = 0, pb3 = 0;
        unsigned long long qa0 = 0, qa1 = 0, qa2 = 0, qa3 = 0;
        unsigned long long qb0 = 0, qb1 = 0, qb2 = 0, qb3 = 0;
        #pragma unroll
        for (int i = 0; i < 16; i += 2) {
            ulonglong2 p0 = ep[i];
            ulonglong2 p1 = ep[i + 1];
            pa0 = fma2(xa[2 * i],     p0.x, pa0);
            pa1 = fma2(xa[2 * i + 1], p0.y, pa1);
            pa2 = fma2(xa[2 * i + 2], p1.x, pa2);
            pa3 = fma2(xa[2 * i + 3], p1.y, pa3);
            pb0 = fma2(xb[2 * i],     p0.x, pb0);
            pb1 = fma2(xb[2 * i + 1], p0.y, pb1);
            pb2 = fma2(xb[2 * i + 2], p1.x, pb2);
            pb3 = fma2(xb[2 * i + 3], p1.y, pb3);
            ulonglong2 q0 = eq[i];
            ulonglong2 q1 = eq[i + 1];
            qa0 = fma2(xa[2 * i],     q0.x, qa0);
            qa1 = fma2(xa[2 * i + 1], q0.y, qa1);
            qa2 = fma2(xa[2 * i + 2], q1.x, qa2);
            qa3 = fma2(xa[2 * i + 3], q1.y, qa3);
            qb0 = fma2(xb[2 * i],     q0.x, qb0);
            qb1 = fma2(xb[2 * i + 1], q0.y, qb1);
            qb2 = fma2(xb[2 * i + 2], q1.x, qb2);
            qb3 = fma2(xb[2 * i + 3], q1.y, qb3);
        }
        float ckP = sc[k];
        float ckQ = sc[CB_HALF + k];
        unsigned long long sP0 = add2(add2(pa0, pa2), add2(pa1, pa3));
        unsigned long long sP1 = add2(add2(pb0, pb2), add2(pb1, pb3));
        unsigned long long sQ0 = add2(add2(qa0, qa2), add2(qa1, qa3));
        unsigned long long sQ1 = add2(add2(qb0, qb2), add2(qb1, qb3));
        float dP0 = lo2(sP0) + hi2(sP0);
        float dP1 = lo2(sP1) + hi2(sP1);
        float dQ0 = lo2(sQ0) + hi2(sQ0);
        float dQ1 = lo2(sQ1) + hi2(sQ1);
        float eP0 = __fadd_rn(__fmaf_rn(-2.0f, dP0, A0), ckP);   // 2*dot exact
        float eP1 = __fadd_rn(__fmaf_rn(-2.0f, dP1, A1), ckP);
        float eQ0 = __fadd_rn(__fmaf_rn(-2.0f, dQ0, A0), ckQ);
        float eQ1 = __fadd_rn(__fmaf_rn(-2.0f, dQ1, A1), ckQ);
        if (eP0 < bestP0) { bestP0 = eP0; bkP0 = k; }            // strict <
        if (eP1 < bestP1) { bestP1 = eP1; bkP1 = k; }
        if (eQ0 < bestQ0) { bestQ0 = eQ0; bkQ0 = k; }
        if (eQ1 < bestQ1) { bestQ1 = eQ1; bkQ1 = k; }
    }
    // cross-half merge: ties keep LOW half (lower global index) -> strict <
    const int bk0 = (bestQ0 < bestP0) ? (CB_HALF + bkQ0) : bkP0;
    const int bk1 = (bestQ1 < bestP1) ? (CB_HALF + bkQ1) : bkP1;

    // --- epilogue: gather e[bk] from GLOBAL (L2-resident), write q + idx, SSE ---
    float sse = 0.f;
    {
        const float4* qe = reinterpret_cast<const float4*>(e_g + (size_t)bk0 * EMB_D);
        float* orow = out + 1 + (size_t)row0 * EMB_D;
        float q[64];
        #pragma unroll
        for (int i = 0; i < 16; i++) {
            float4 qq = qe[i];
            q[4 * i] = qq.x; q[4 * i + 1] = qq.y; q[4 * i + 2] = qq.z; q[4 * i + 3] = qq.w;
        }
        #pragma unroll
        for (int i = 0; i < 32; i++) {
            float d0 = q[2 * i]     - lo2(xa[i]);
            float d1 = q[2 * i + 1] - hi2(xa[i]);
            sse = __fmaf_rn(d0, d0, sse);
            sse = __fmaf_rn(d1, d1, sse);
        }
        orow[0] = q[0]; orow[1] = q[1]; orow[2] = q[2];
        float4* ov = reinterpret_cast<float4*>(orow + 3);
        #pragma unroll
        for (int i = 0; i < 15; i++) {
            float4 v;
            v.x = q[3 + 4 * i]; v.y = q[4 + 4 * i];
            v.z = q[5 + 4 * i]; v.w = q[6 + 4 * i];
            ov[i] = v;
        }
        orow[63] = q[63];
        out[1 + Q_ELEMS + (size_t)row0] = (float)bk0;
    }
    {
        const float4* qe = reinterpret_cast<const float4*>(e_g + (size_t)bk1 * EMB_D);
        float* orow = out + 1 + (size_t)row1 * EMB_D;
        float q[64];
        #pragma unroll
        for (int i = 0; i < 16; i++) {
            float4 qq = qe[i];
            q[4 * i] = qq.x; q[4 * i + 1] = qq.y; q[4 * i + 2] = qq.z; q[4 * i + 3] = qq.w;
        }
        #pragma unroll
        for (int i = 0; i < 32; i++) {
            float d0 = q[2 * i]     - lo2(xb[i]);
            float d1 = q[2 * i + 1] - hi2(xb[i]);
            sse = __fmaf_rn(d0, d0, sse);
            sse = __fmaf_rn(d1, d1, sse);
        }
        orow[0] = q[0]; orow[1] = q[1]; orow[2] = q[2];
        float4* ov = reinterpret_cast<float4*>(orow + 3);
        #pragma unroll
        for (int i = 0; i < 15; i++) {
            float4 v;
            v.x = q[3 + 4 * i]; v.y = q[4 + 4 * i];
            v.z = q[5 + 4 * i]; v.w = q[6 + 4 * i];
            ov[i] = v;
        }
        orow[63] = q[63];
        out[1 + Q_ELEMS + (size_t)row1] = (float)bk1;
    }

    // --- CTA loss reduction (deterministic tree) ---
    sred[tid] = sse;
    __syncthreads();
    #pragma unroll
    for (int off = THREADS / 2; off > 0; off >>= 1) {
        if (tid < off) sred[tid] = sred[tid] + sred[tid + off];
        __syncthreads();
    }
    if (tid == 0) g_partial[blockIdx.x] = sred[0];
}

// Final deterministic reduce over 128 CTA partials: loss = 1.25 * SSE / (N*D)
__global__ void vq_reduce_kernel(float* __restrict__ out) {
    __shared__ double sd[N_CTA];
    int tid = threadIdx.x;
    sd[tid] = (double)g_partial[tid];
    __syncthreads();
    #pragma unroll
    for (int off = N_CTA / 2; off > 0; off >>= 1) {
        if (tid < off) sd[tid] = sd[tid] + sd[tid + off];
        __syncthreads();
    }
    if (tid == 0) {
        double mean = sd[0] / (double)((size_t)N_ROWS * EMB_D);
        out[0] = (float)(1.25 * mean);   // q_latent + 0.25 * e_latent
    }
}

extern "C" void kernel_launch(void* const* d_in, const int* in_sizes, int n_in,
                              void* d_out, int out_size) {
    const float* x = (const float*)d_in[0];
    const float* e = (const float*)d_in[1];
    if (n_in >= 2 && in_sizes[0] == CB_K * EMB_D) {
        const float* t = x; x = e; e = t;
    }
    float* out = (float*)d_out;

    // Fill constant bank with HIGH half of the codebook (64 KB, D2D, capturable)
    cudaMemcpyToSymbolAsync(c_ehi, e + (size_t)CB_HALF * EMB_D,
                            CB_HALF * EMB_D * sizeof(float), 0,
                            cudaMemcpyDeviceToDevice);

    cudaFuncSetAttribute(vq_main_kernel,
                         cudaFuncAttributeMaxDynamicSharedMemorySize, SMEM_BYTES);
    vq_main_kernel<<<N_CTA, THREADS, SMEM_BYTES>>>(x, e, out);
    vq_reduce_kernel<<<1, N_CTA>>>(out);
}